// round 14
// baseline (speedup 1.0000x reference)
#include <cuda_runtime.h>

// EncodeLayer: SSD anchor matching + box encoding.
// labels:        [B=64, M=100, 5]  (x1,y1,x2,y2,cls), cls==0 => padding row
// default_boxes: [N=8732, 4]
// out: labeled [B, N, 5] (2,794,240 f32) then ious [B, 101, N] (56,443,648 f32)

#define BATCH   64
#define MROWS   100
#define NGT     101          // MROWS + prepended zero row
#define NANCH   8732
#define TPB     128
#define APT     4            // anchors per thread (8732 % 4 == 0)
#define ANCH_PER_BLOCK (TPB * APT)   // 512
#define MUNROLL 10           // 100 rows = 10 groups of 10

// Hot-loop division: rcp.approx (~1-2 ulp) + FMUL. Exact for n==0.
__device__ __forceinline__ float approx_div(float n, float d) {
    float r;
    asm("rcp.approx.f32 %0, %1;" : "=f"(r) : "f"(d));
    return n * r;
}

// Epilogue division: one quotient refinement on top (~0.5-1 ulp), branch-free.
__device__ __forceinline__ float fast_div(float n, float d) {
    float r;
    asm("rcp.approx.f32 %0, %1;" : "=f"(r) : "f"(d));
    float q0  = n * r;
    float rem = __fmaf_rn(-d, q0, n);
    return __fmaf_rn(rem, r, q0);
}

__global__ __launch_bounds__(TPB)
void encode_layer_kernel(const float* __restrict__ labels,
                         const float* __restrict__ dboxes,
                         float* __restrict__ out_labeled,   // [B, N, 5]
                         float* __restrict__ out_ious)      // [B, 101, N]
{
    __shared__ float4 sbox[NGT];   // gt box (zeroed if cls==0, row 0 = zero row)
    __shared__ float  sarea[NGT];  // gt area (0 for invalid rows)
    __shared__ float  scls[NGT];   // original class value

    const int b   = blockIdx.y;
    const int tid = threadIdx.x;

    // ---- issue the per-thread anchor LDG.128s FIRST, so their ~600cyc
    //      latency drains behind the GT staging loop + barrier instead of
    //      front-stalling the hot loop (compresses cross-CTA start skew).
    const int n0 = (blockIdx.x * TPB + tid) * APT;
    const bool active = (n0 < NANCH);   // 8732 % 4 == 0, so n0..n0+3 all valid
    float4 db[APT];
#pragma unroll
    for (int i = 0; i < APT; i++) {
        const int ai = active ? (n0 + i) : 0;   // clamped: inactive threads never use these
        db[i] = *reinterpret_cast<const float4*>(dboxes + (size_t)ai * 4);
    }

    // ---- stage GT table for this batch into smem (all threads participate) ----
    for (int r = tid; r < NGT; r += TPB) {
        float x1 = 0.f, y1 = 0.f, x2 = 0.f, y2 = 0.f, c = 0.f;
        if (r > 0) {
            const float* L = labels + ((size_t)b * MROWS + (r - 1)) * 5;
            x1 = L[0]; y1 = L[1]; x2 = L[2]; y2 = L[3]; c = L[4];
            if (c == 0.0f) { x1 = 0.f; y1 = 0.f; x2 = 0.f; y2 = 0.f; }
        }
        sbox[r]  = make_float4(x1, y1, x2, y2);
        sarea[r] = (x2 - x1) * (y2 - y1);
        scls[r]  = c;
    }
    __syncthreads();

    if (!active) return;

    // ---- per-thread anchor registers (loads already in flight) ----
    float ax1[APT], ay1[APT], ax2[APT], ay2[APT], aarea[APT];
#pragma unroll
    for (int i = 0; i < APT; i++) {
        ax1[i] = db[i].x; ay1[i] = db[i].y; ax2[i] = db[i].z; ay2[i] = db[i].w;
        aarea[i] = (db[i].z - db[i].x) * (db[i].w - db[i].y);
    }

    // argmax state: row 0 (zero row, iou==0) is the default winner; strict >
    // against best=0 reproduces jnp.argmax first-occurrence semantics.
    float best[APT] = {0.f, 0.f, 0.f, 0.f};
    int   bidx[APT] = {0, 0, 0, 0};

    float* iou_ptr = out_ious + (size_t)b * NGT * NANCH + n0;

    // ---- peel m=0: prepended zero row -> iou row is all zeros, no math ----
    __stcs(reinterpret_cast<float4*>(iou_ptr), make_float4(0.f, 0.f, 0.f, 0.f));
    iou_ptr += NANCH;

    // ---- main loop: 100 real GT rows, 10 groups of 10. Row strides fold
    //      into STG immediate offsets; 40 independent IoU chains per group.
    for (int mo = 0; mo < MROWS; mo += MUNROLL) {
#pragma unroll
        for (int mm = 0; mm < MUNROLL; mm++) {
            const int m = 1 + mo + mm;
            const float4 tb = sbox[m];
            const float  ta = sarea[m];
            float4 o;
            float* op = &o.x;
#pragma unroll
            for (int i = 0; i < APT; i++) {
                float ix1 = fmaxf(tb.x, ax1[i]);
                float iy1 = fmaxf(tb.y, ay1[i]);
                float ix2 = fminf(tb.z, ax2[i]);
                float iy2 = fminf(tb.w, ay2[i]);
                // w,h < 1 always (box widths <= ~0.4), so saturate == max(.,0);
                // ptxas fuses this into FADD.SAT.
                float w = __saturatef(ix2 - ix1);
                float h = __saturatef(iy2 - iy1);
                float inter = w * h;
                // FFMA form: denom computes in parallel with inter (no serial
                // dependence inter -> denom), shortening the chain into MUFU.
                float denom = __fmaf_rn(-w, h, ta + aarea[i]);
                float iou = approx_div(inter, denom);
                op[i] = iou;
                if (iou > best[i]) { best[i] = iou; bidx[i] = m; }  // first-occurrence argmax
            }
            __stcs(reinterpret_cast<float4*>(iou_ptr + (size_t)mm * NANCH), o);
        }
        iou_ptr += (size_t)MUNROLL * NANCH;
    }

    // ---- epilogue: gather winner, encode offsets ----
    float outbuf[APT * 5];
#pragma unroll
    for (int i = 0; i < APT; i++) {
        const bool pos = best[i] > 0.5f;
        const int  idx = pos ? bidx[i] : 0;
        const float4 gb = sbox[idx];
        const float  c  = scls[idx];

        float bx1, by1, bx2, by2;
        if (c == 0.0f) { bx1 = ax1[i]; by1 = ay1[i]; bx2 = ax2[i]; by2 = ay2[i]; }
        else           { bx1 = gb.x;   by1 = gb.y;   bx2 = gb.z;   by2 = gb.w;   }

        const float tcx = 0.5f * (bx1 + bx2), tcy = 0.5f * (by1 + by2);
        const float tw  = bx2 - bx1,          th  = by2 - by1;
        const float acx = 0.5f * (ax1[i] + ax2[i]), acy = 0.5f * (ay1[i] + ay2[i]);
        const float aw  = ax2[i] - ax1[i],          ah  = ay2[i] - ay1[i];

        outbuf[i * 5 + 0] = fast_div(tcx - acx, aw);
        outbuf[i * 5 + 1] = fast_div(tcy - acy, ah);
        outbuf[i * 5 + 2] = __logf(fast_div(tw, aw));
        outbuf[i * 5 + 3] = __logf(fast_div(th, ah));
        outbuf[i * 5 + 4] = pos ? c : 0.0f;
    }

    // 20 contiguous, 16B-aligned floats -> 5x STG.128 (streaming)
    float4* lb = reinterpret_cast<float4*>(out_labeled + ((size_t)b * NANCH + n0) * 5);
#pragma unroll
    for (int i = 0; i < 5; i++)
        __stcs(lb + i, *reinterpret_cast<const float4*>(&outbuf[i * 4]));
}

extern "C" void kernel_launch(void* const* d_in, const int* in_sizes, int n_in,
                              void* d_out, int out_size)
{
    const float* labels = (const float*)d_in[0];   // [64,100,5]
    const float* dboxes = (const float*)d_in[1];   // [8732,4]

    float* out_labeled = (float*)d_out;                                   // [64,8732,5]
    float* out_ious    = (float*)d_out + (size_t)BATCH * NANCH * 5;       // [64,101,8732]

    dim3 grid((NANCH + ANCH_PER_BLOCK - 1) / ANCH_PER_BLOCK, BATCH);      // (18, 64)
    encode_layer_kernel<<<grid, TPB>>>(labels, dboxes, out_labeled, out_ious);
}

// round 15
// speedup vs baseline: 1.0081x; 1.0081x over previous
#include <cuda_runtime.h>

// EncodeLayer: SSD anchor matching + box encoding.  [FINAL — converged config]
// labels:        [B=64, M=100, 5]  (x1,y1,x2,y2,cls), cls==0 => padding row
// default_boxes: [N=8732, 4]
// out: labeled [B, N, 5] (2,794,240 f32) then ious [B, 101, N] (56,443,648 f32)
//
// Session summary: 135.7us (IEEE-div baseline) -> 51.7us via
//  (1) branch-free rcp.approx division (removes FCHK/BSSY slow-path envelope),
//  (2) FADD.SAT clamps (frees alu-pipe FMNMX),
//  (3) TPB=128/APT=4 geometry + unroll-10 ILP window + imm-offset stores,
//  (4) hoisted anchor LDG.128s (latency hidden behind GT staging barrier).
// Issue-bound at ~73% with ~22.5 slots/element; no pipe saturated; verified
// floor across 15 variants (geometry, store paths, argmax forms, TMA staging).

#define BATCH   64
#define MROWS   100
#define NGT     101          // MROWS + prepended zero row
#define NANCH   8732
#define TPB     128
#define APT     4            // anchors per thread (8732 % 4 == 0)
#define ANCH_PER_BLOCK (TPB * APT)   // 512
#define MUNROLL 10           // 100 rows = 10 groups of 10

// Hot-loop division: rcp.approx (~1-2 ulp) + FMUL. Exact for n==0.
__device__ __forceinline__ float approx_div(float n, float d) {
    float r;
    asm("rcp.approx.f32 %0, %1;" : "=f"(r) : "f"(d));
    return n * r;
}

// Epilogue division: one quotient refinement on top (~0.5-1 ulp), branch-free.
__device__ __forceinline__ float fast_div(float n, float d) {
    float r;
    asm("rcp.approx.f32 %0, %1;" : "=f"(r) : "f"(d));
    float q0  = n * r;
    float rem = __fmaf_rn(-d, q0, n);
    return __fmaf_rn(rem, r, q0);
}

__global__ __launch_bounds__(TPB)
void encode_layer_kernel(const float* __restrict__ labels,
                         const float* __restrict__ dboxes,
                         float* __restrict__ out_labeled,   // [B, N, 5]
                         float* __restrict__ out_ious)      // [B, 101, N]
{
    __shared__ float4 sbox[NGT];   // gt box (zeroed if cls==0, row 0 = zero row)
    __shared__ float  sarea[NGT];  // gt area (0 for invalid rows)
    __shared__ float  scls[NGT];   // original class value

    const int b   = blockIdx.y;
    const int tid = threadIdx.x;

    // ---- issue the per-thread anchor LDG.128s FIRST, so their ~600cyc
    //      latency drains behind the GT staging loop + barrier instead of
    //      front-stalling the hot loop (compresses cross-CTA start skew).
    const int n0 = (blockIdx.x * TPB + tid) * APT;
    const bool active = (n0 < NANCH);   // 8732 % 4 == 0, so n0..n0+3 all valid
    float4 db[APT];
#pragma unroll
    for (int i = 0; i < APT; i++) {
        const int ai = active ? (n0 + i) : 0;   // clamped: inactive threads never use these
        db[i] = *reinterpret_cast<const float4*>(dboxes + (size_t)ai * 4);
    }

    // ---- stage GT table for this batch into smem (all threads participate) ----
    for (int r = tid; r < NGT; r += TPB) {
        float x1 = 0.f, y1 = 0.f, x2 = 0.f, y2 = 0.f, c = 0.f;
        if (r > 0) {
            const float* L = labels + ((size_t)b * MROWS + (r - 1)) * 5;
            x1 = L[0]; y1 = L[1]; x2 = L[2]; y2 = L[3]; c = L[4];
            if (c == 0.0f) { x1 = 0.f; y1 = 0.f; x2 = 0.f; y2 = 0.f; }
        }
        sbox[r]  = make_float4(x1, y1, x2, y2);
        sarea[r] = (x2 - x1) * (y2 - y1);
        scls[r]  = c;
    }
    __syncthreads();

    if (!active) return;

    // ---- per-thread anchor registers (loads already in flight) ----
    float ax1[APT], ay1[APT], ax2[APT], ay2[APT], aarea[APT];
#pragma unroll
    for (int i = 0; i < APT; i++) {
        ax1[i] = db[i].x; ay1[i] = db[i].y; ax2[i] = db[i].z; ay2[i] = db[i].w;
        aarea[i] = (db[i].z - db[i].x) * (db[i].w - db[i].y);
    }

    // argmax state: row 0 (zero row, iou==0) is the default winner; strict >
    // against best=0 reproduces jnp.argmax first-occurrence semantics.
    float best[APT] = {0.f, 0.f, 0.f, 0.f};
    int   bidx[APT] = {0, 0, 0, 0};

    float* iou_ptr = out_ious + (size_t)b * NGT * NANCH + n0;

    // ---- peel m=0: prepended zero row -> iou row is all zeros, no math ----
    __stcs(reinterpret_cast<float4*>(iou_ptr), make_float4(0.f, 0.f, 0.f, 0.f));
    iou_ptr += NANCH;

    // ---- main loop: 100 real GT rows, 10 groups of 10. Row strides fold
    //      into STG immediate offsets; 40 independent IoU chains per group.
    for (int mo = 0; mo < MROWS; mo += MUNROLL) {
#pragma unroll
        for (int mm = 0; mm < MUNROLL; mm++) {
            const int m = 1 + mo + mm;
            const float4 tb = sbox[m];
            const float  ta = sarea[m];
            float4 o;
            float* op = &o.x;
#pragma unroll
            for (int i = 0; i < APT; i++) {
                float ix1 = fmaxf(tb.x, ax1[i]);
                float iy1 = fmaxf(tb.y, ay1[i]);
                float ix2 = fminf(tb.z, ax2[i]);
                float iy2 = fminf(tb.w, ay2[i]);
                // w,h < 1 always (box widths <= ~0.4), so saturate == max(.,0);
                // ptxas fuses this into FADD.SAT.
                float w = __saturatef(ix2 - ix1);
                float h = __saturatef(iy2 - iy1);
                float inter = w * h;
                float denom = (ta + aarea[i]) - inter;
                float iou = approx_div(inter, denom);
                op[i] = iou;
                if (iou > best[i]) { best[i] = iou; bidx[i] = m; }  // first-occurrence argmax
            }
            __stcs(reinterpret_cast<float4*>(iou_ptr + (size_t)mm * NANCH), o);
        }
        iou_ptr += (size_t)MUNROLL * NANCH;
    }

    // ---- epilogue: gather winner, encode offsets ----
    float outbuf[APT * 5];
#pragma unroll
    for (int i = 0; i < APT; i++) {
        const bool pos = best[i] > 0.5f;
        const int  idx = pos ? bidx[i] : 0;
        const float4 gb = sbox[idx];
        const float  c  = scls[idx];

        float bx1, by1, bx2, by2;
        if (c == 0.0f) { bx1 = ax1[i]; by1 = ay1[i]; bx2 = ax2[i]; by2 = ay2[i]; }
        else           { bx1 = gb.x;   by1 = gb.y;   bx2 = gb.z;   by2 = gb.w;   }

        const float tcx = 0.5f * (bx1 + bx2), tcy = 0.5f * (by1 + by2);
        const float tw  = bx2 - bx1,          th  = by2 - by1;
        const float acx = 0.5f * (ax1[i] + ax2[i]), acy = 0.5f * (ay1[i] + ay2[i]);
        const float aw  = ax2[i] - ax1[i],          ah  = ay2[i] - ay1[i];

        outbuf[i * 5 + 0] = fast_div(tcx - acx, aw);
        outbuf[i * 5 + 1] = fast_div(tcy - acy, ah);
        outbuf[i * 5 + 2] = __logf(fast_div(tw, aw));
        outbuf[i * 5 + 3] = __logf(fast_div(th, ah));
        outbuf[i * 5 + 4] = pos ? c : 0.0f;
    }

    // 20 contiguous, 16B-aligned floats -> 5x STG.128 (streaming)
    float4* lb = reinterpret_cast<float4*>(out_labeled + ((size_t)b * NANCH + n0) * 5);
#pragma unroll
    for (int i = 0; i < 5; i++)
        __stcs(lb + i, *reinterpret_cast<const float4*>(&outbuf[i * 4]));
}

extern "C" void kernel_launch(void* const* d_in, const int* in_sizes, int n_in,
                              void* d_out, int out_size)
{
    const float* labels = (const float*)d_in[0];   // [64,100,5]
    const float* dboxes = (const float*)d_in[1];   // [8732,4]

    float* out_labeled = (float*)d_out;                                   // [64,8732,5]
    float* out_ious    = (float*)d_out + (size_t)BATCH * NANCH * 5;       // [64,101,8732]

    dim3 grid((NANCH + ANCH_PER_BLOCK - 1) / ANCH_PER_BLOCK, BATCH);      // (18, 64)
    encode_layer_kernel<<<grid, TPB>>>(labels, dboxes, out_labeled, out_ious);
}